// round 9
// baseline (speedup 1.0000x reference)
#include <cuda_runtime.h>
#include <cuda_bf16.h>
#include <math.h>

// ---------------------------------------------------------------------------
// GPTrack2D encoder — tf32 mma.sync, cp.async 3-stage pipeline, batched
// loop-invariant qkv half. B=2, L=12, N=1024, D=768, H=12, M=3072, 2 layers.
// (Resubmission of R6 kernel — previous bench died to container infra, no
// measurement was taken.)
// ---------------------------------------------------------------------------

#define Bc 2
#define Lc 12
#define Nc 1024
#define Dc 768
#define Hc 12
#define Mc 3072
#define D3c 2304
#define BNc (Bc*Nc)          /* 2048 */
#define BLNc (Bc*Lc*Nc)      /* 24576 */
#define NDc (Nc*Dc)
#define LNDc (Lc*Nc*Dc)
#define TOTc (Bc*Lc*Nc*Dc)
#define BNDc (Bc*Nc*Dc)

// ------------------------- device scratch (no allocs) ----------------------
__device__ float g_pos   [TOTc];
__device__ float g_x     [TOTc];
__device__ float g_y     [TOTc];
__device__ float g_h     [BNDc];
__device__ float g_hn    [BNDc];
__device__ float g_xnall [BLNc*Dc];
__device__ float g_qkvpre[(long)BLNc*D3c];
__device__ float g_qkv   [BNc*D3c];
__device__ float g_kvp   [Bc*Hc*8*64*64];
__device__ float g_o     [BNDc];
__device__ float g_x2    [BNDc];
__device__ float g_ln2   [BNDc];
__device__ float g_t1    [BNc*Mc];

__device__ __forceinline__ float gelu_f(float x) {
    return 0.5f * x * (1.0f + erff(x * 0.70710678118654752440f));
}
__device__ __forceinline__ unsigned f2tf32(float x) {
    unsigned r;
    asm("cvt.rna.tf32.f32 %0, %1;" : "=r"(r) : "f"(x));
    return r;
}
__device__ __forceinline__ void mma_tf32(float c[4], unsigned a0, unsigned a1,
                                         unsigned a2, unsigned a3,
                                         unsigned b0, unsigned b1) {
    asm volatile(
        "mma.sync.aligned.m16n8k8.row.col.f32.tf32.tf32.f32 "
        "{%0,%1,%2,%3},{%4,%5,%6,%7},{%8,%9},{%0,%1,%2,%3};"
        : "+f"(c[0]), "+f"(c[1]), "+f"(c[2]), "+f"(c[3])
        : "r"(a0), "r"(a1), "r"(a2), "r"(a3), "r"(b0), "r"(b1));
}
__device__ __forceinline__ void cp16(void* sdst, const void* gsrc) {
    unsigned s = (unsigned)__cvta_generic_to_shared(sdst);
    asm volatile("cp.async.cg.shared.global [%0], [%1], 16;" :: "r"(s), "l"(gsrc));
}

// ------------------------------- elementwise -------------------------------
__global__ void pos_kernel(const float* __restrict__ tpos,
                           const float* __restrict__ spos,
                           float* __restrict__ pos) {
    int idx = blockIdx.x * blockDim.x + threadIdx.x;
    if (idx >= TOTc) return;
    int d = idx % Dc;
    int n = (idx / Dc) % Nc;
    int l = (idx / NDc) % Lc;
    int b = idx / LNDc;
    pos[idx] = tpos[(b * Lc + l) * Dc + d] * spos[(b * Nc + n) * Dc + d];
}
__global__ void vadd_kernel(const float* __restrict__ a,
                            const float* __restrict__ b,
                            float* __restrict__ c, int n) {
    int idx = blockIdx.x * blockDim.x + threadIdx.x;
    if (idx < n) c[idx] = a[idx] + b[idx];
}
__global__ void copy_kernel(const float* __restrict__ a,
                            float* __restrict__ b, int n) {
    int idx = blockIdx.x * blockDim.x + threadIdx.x;
    if (idx < n) b[idx] = a[idx];
}

// ------------------------------- layernorm ---------------------------------
__device__ __forceinline__ void ln_row(float v0, float v1, float v2,
                                       const float* __restrict__ gam,
                                       const float* __restrict__ bet,
                                       float* __restrict__ dp, int t,
                                       float* red) {
    float s = v0 + v1 + v2;
    #pragma unroll
    for (int o = 16; o > 0; o >>= 1) s += __shfl_down_sync(0xffffffffu, s, o);
    if ((t & 31) == 0) red[t >> 5] = s;
    __syncthreads();
    if (t < 32) {
        float x = (t < 8) ? red[t] : 0.0f;
        #pragma unroll
        for (int o = 4; o > 0; o >>= 1) x += __shfl_down_sync(0xffffffffu, x, o);
        if (t == 0) red[0] = x;
    }
    __syncthreads();
    float m = red[0] * (1.0f / 768.0f);
    __syncthreads();
    float d0 = v0 - m, d1 = v1 - m, d2 = v2 - m;
    float q2 = d0 * d0 + d1 * d1 + d2 * d2;
    #pragma unroll
    for (int o = 16; o > 0; o >>= 1) q2 += __shfl_down_sync(0xffffffffu, q2, o);
    if ((t & 31) == 0) red[t >> 5] = q2;
    __syncthreads();
    if (t < 32) {
        float x = (t < 8) ? red[t] : 0.0f;
        #pragma unroll
        for (int o = 4; o > 0; o >>= 1) x += __shfl_down_sync(0xffffffffu, x, o);
        if (t == 0) red[0] = x;
    }
    __syncthreads();
    float r = rsqrtf(red[0] * (1.0f / 768.0f) + 1e-5f);
    dp[t]       = d0 * r * gam[t]       + bet[t];
    dp[t + 256] = d1 * r * gam[t + 256] + bet[t + 256];
    dp[t + 512] = d2 * r * gam[t + 512] + bet[t + 512];
}

// per-step LN (2048 rows), optional add source
__global__ void ln_step(const float* __restrict__ src, int bstride, int soff,
                        const float* __restrict__ add, int abstride, int aoff,
                        const float* __restrict__ gam,
                        const float* __restrict__ bet,
                        float* __restrict__ dst) {
    __shared__ float red[32];
    int row = blockIdx.x;
    int b = row >> 10, n = row & 1023;
    const float* p = src + (long)b * bstride + soff + (long)n * Dc;
    int t = threadIdx.x;
    float v0 = p[t], v1 = p[t + 256], v2 = p[t + 512];
    if (add) {
        const float* q = add + (long)b * abstride + aoff + (long)n * Dc;
        v0 += q[t]; v1 += q[t + 256]; v2 += q[t + 512];
    }
    ln_row(v0, v1, v2, gam, bet, dst + (long)row * Dc, t, red);
}

// batched LN over all timesteps: out rows R = t*2048 + b*1024 + n
__global__ void ln_xall(const float* __restrict__ X,
                        const float* __restrict__ gam,
                        const float* __restrict__ bet,
                        float* __restrict__ dst) {
    __shared__ float red[32];
    int R = blockIdx.x;
    int tt = R / BNc;
    int rr = R - tt * BNc;
    int b = rr >> 10, n = rr & 1023;
    const float* p = X + (long)b * LNDc + (long)tt * NDc + (long)n * Dc;
    int t = threadIdx.x;
    ln_row(p[t], p[t + 256], p[t + 512], gam, bet, dst + (long)R * Dc, t, red);
}

// ----------------------------- tf32 MMA GEMM -------------------------------
// BM=128, BN=64, BK=16, 128 threads (4 warps, warp tile 64x32), 3-stage
// cp.async pipeline. EPI: 0 plain+bias, 1 gelu, 2 qkv-step(+pre, elu on
// cols<1536), 3 Wout-residual, 4 W2-ywrite.
struct EpiAux {
    const float* pre;              // EPI2
    const float* X;   int xoff;    // EPI3
    float* h;                      // EPI3
    const float* pos; int tpoff;   // EPI3
    float* x2w;                    // EPI3
    const float* x2r;              // EPI4
    float* y; int yoff; int add;   // EPI4
};

template<int EPI>
__global__ void __launch_bounds__(128)
tgemm(const float* __restrict__ A, int lda,
      const float* __restrict__ B, int ldb,
      const float* __restrict__ bias, float* __restrict__ C,
      int N, int K, EpiAux aux) {
    constexpr int BM = 128, BN = 64, BK = 16;
    __shared__ float As[3][BM][20];
    __shared__ float Bs[3][BK][68];

    const int tid = threadIdx.x;
    const int lane = tid & 31;
    const int wid = tid >> 5;
    const int warp_m = (wid >> 1) * 64;
    const int warp_n = (wid & 1) * 32;
    const int bx = blockIdx.x, by = blockIdx.y;
    const int r = lane >> 2, cq = lane & 3;

    float acc[4][4][4];
    #pragma unroll
    for (int i = 0; i < 4; i++)
        #pragma unroll
        for (int j = 0; j < 4; j++)
            #pragma unroll
            for (int q = 0; q < 4; q++) acc[i][j][q] = 0.0f;

    const int S = K / BK;

    auto issue_stage = [&](int s) {
        int st = s % 3;
        int k0 = s * BK;
        #pragma unroll
        for (int i = 0; i < 4; i++) {                 // A: 512 float4 slots
            int lid = tid + i * 128;
            int am = lid >> 2, ak = (lid & 3) * 4;
            cp16(&As[st][am][ak], A + (long)(by * BM + am) * lda + k0 + ak);
        }
        #pragma unroll
        for (int i = 0; i < 2; i++) {                 // B: 256 float4 slots
            int lid = tid + i * 128;
            int br = lid >> 4, bc = (lid & 15) * 4;
            cp16(&Bs[st][br][bc], B + (long)(k0 + br) * ldb + bx * BN + bc);
        }
    };

    issue_stage(0);
    asm volatile("cp.async.commit_group;");
    issue_stage(1);
    asm volatile("cp.async.commit_group;");

    for (int s = 0; s < S; s++) {
        asm volatile("cp.async.wait_group 1;");
        __syncthreads();
        if (s + 2 < S) issue_stage(s + 2);
        asm volatile("cp.async.commit_group;");
        const int buf = s % 3;
        #pragma unroll
        for (int ka = 0; ka < 2; ka++) {
            const int kb = ka * 8;
            unsigned af[4][4], bf[4][2];
            #pragma unroll
            for (int mi = 0; mi < 4; mi++) {
                int m0 = warp_m + mi * 16 + r;
                af[mi][0] = f2tf32(As[buf][m0][kb + cq]);
                af[mi][1] = f2tf32(As[buf][m0 + 8][kb + cq]);
                af[mi][2] = f2tf32(As[buf][m0][kb + cq + 4]);
                af[mi][3] = f2tf32(As[buf][m0 + 8][kb + cq + 4]);
            }
            #pragma unroll
            for (int ni = 0; ni < 4; ni++) {
                int n0 = warp_n + ni * 8 + r;
                bf[ni][0] = f2tf32(Bs[buf][kb + cq][n0]);
                bf[ni][1] = f2tf32(Bs[buf][kb + cq + 4][n0]);
            }
            #pragma unroll
            for (int mi = 0; mi < 4; mi++)
                #pragma unroll
                for (int ni = 0; ni < 4; ni++)
                    mma_tf32(acc[mi][ni], af[mi][0], af[mi][1], af[mi][2],
                             af[mi][3], bf[ni][0], bf[ni][1]);
        }
        __syncthreads();
    }

    // ---- epilogue ----
    #pragma unroll
    for (int mi = 0; mi < 4; mi++) {
        #pragma unroll
        for (int ni = 0; ni < 4; ni++) {
            int col = bx * BN + warp_n + ni * 8 + 2 * cq;
            float bs0 = bias[col], bs1 = bias[col + 1];
            #pragma unroll
            for (int half = 0; half < 2; half++) {
                int row = by * BM + warp_m + mi * 16 + r + half * 8;
                float v0 = acc[mi][ni][half * 2 + 0] + bs0;
                float v1 = acc[mi][ni][half * 2 + 1] + bs1;
                if (EPI == 0) {
                    float* cp = C + (long)row * N + col;
                    cp[0] = v0; cp[1] = v1;
                } else if (EPI == 1) {
                    float* cp = C + (long)row * N + col;
                    cp[0] = gelu_f(v0); cp[1] = gelu_f(v1);
                } else if (EPI == 2) {
                    long idx = (long)row * N + col;
                    v0 += aux.pre[idx];
                    v1 += aux.pre[idx + 1];
                    if (col < 1536)     v0 = (v0 > 0.f) ? v0 + 1.f : expf(v0);
                    if (col + 1 < 1536) v1 = (v1 > 0.f) ? v1 + 1.f : expf(v1);
                    float* cp = C + idx;
                    cp[0] = v0; cp[1] = v1;
                } else if (EPI == 3) {
                    int b = row >> 10, rr = row & 1023;
                    long base = (long)b * LNDc + (long)rr * Dc + col;
                    long idx = (long)row * Dc + col;
                    aux.x2w[idx]     = v0 + aux.X[base + aux.xoff];
                    aux.x2w[idx + 1] = v1 + aux.X[base + aux.xoff + 1];
                    aux.h[idx]     = v0 + aux.h[idx]     + aux.pos[base + aux.tpoff];
                    aux.h[idx + 1] = v1 + aux.h[idx + 1] + aux.pos[base + aux.tpoff + 1];
                } else if (EPI == 4) {
                    int b = row >> 10, rr = row & 1023;
                    long idx = (long)row * Dc + col;
                    float w0 = v0 + aux.x2r[idx];
                    float w1 = v1 + aux.x2r[idx + 1];
                    long yo = (long)b * LNDc + aux.yoff + (long)rr * Dc + col;
                    if (aux.add) { aux.y[yo] += w0; aux.y[yo + 1] += w1; }
                    else         { aux.y[yo]  = w0; aux.y[yo + 1]  = w1; }
                }
            }
        }
    }
}

// ----------------------- linear-attention small GEMMs ----------------------
__global__ void kv_partial_kernel(const float* __restrict__ qkv,
                                  float* __restrict__ kvp) {
    int chunk = blockIdx.x & 7;
    int bh = blockIdx.x >> 3;
    int h = bh % Hc, b = bh / Hc;
    int t = threadIdx.x;
    __shared__ float ks[8][64], vs[8][64];
    int d0 = (t & 15) * 4, e0 = (t >> 4) * 4;
    float acc[4][4];
    #pragma unroll
    for (int i = 0; i < 4; i++)
        #pragma unroll
        for (int j = 0; j < 4; j++) acc[i][j] = 0.0f;
    int j0 = chunk * 128;
    const float* kbase = qkv + (long)(b * Nc) * D3c + Dc + h * 64;
    const float* vbase = kbase + Dc;
    for (int js = 0; js < 128; js += 8) {
        #pragma unroll
        for (int rr = 0; rr < 2; rr++) {
            int id = t + rr * 256;
            int jj = id >> 6, dd = id & 63;
            long roff = (long)(j0 + js + jj) * D3c + dd;
            ks[jj][dd] = kbase[roff];
            vs[jj][dd] = vbase[roff];
        }
        __syncthreads();
        #pragma unroll
        for (int jj = 0; jj < 8; jj++) {
            float kd[4], ve[4];
            *(float4*)kd = *(const float4*)&ks[jj][d0];
            *(float4*)ve = *(const float4*)&vs[jj][e0];
            #pragma unroll
            for (int i = 0; i < 4; i++)
                #pragma unroll
                for (int j = 0; j < 4; j++)
                    acc[i][j] = fmaf(kd[i], ve[j], acc[i][j]);
        }
        __syncthreads();
    }
    float* dst = kvp + ((long)bh * 8 + chunk) * 4096;
    #pragma unroll
    for (int i = 0; i < 4; i++)
        #pragma unroll
        for (int j = 0; j < 4; j++)
            dst[(d0 + i) * 64 + e0 + j] = acc[i][j];
}

__global__ void o_kernel(const float* __restrict__ qkv,
                         const float* __restrict__ kvp,
                         float* __restrict__ o) {
    int ic = blockIdx.x & 7;
    int bh = blockIdx.x >> 3;
    int h = bh % Hc, b = bh / Hc;
    int t = threadIdx.x;
    __shared__ float kvs[4096];
    const float* src = kvp + (long)bh * 8 * 4096;
    for (int x = t; x < 4096; x += 256) {
        float s = 0.0f;
        #pragma unroll
        for (int c = 0; c < 8; c++) s += src[c * 4096 + x];
        kvs[x] = s;
    }
    __syncthreads();
    int i = ic * 128 + (t >> 1);
    int e0 = (t & 1) * 32;
    const float* qrow = qkv + (long)(b * Nc + i) * D3c + h * 64;
    float acc[32];
    #pragma unroll
    for (int g = 0; g < 32; g++) acc[g] = 0.0f;
    #pragma unroll 4
    for (int d = 0; d < 64; d++) {
        float qv = qrow[d];
        #pragma unroll
        for (int g = 0; g < 8; g++) {
            float4 kvv = *(const float4*)&kvs[d * 64 + e0 + g * 4];
            acc[g * 4 + 0] = fmaf(qv, kvv.x, acc[g * 4 + 0]);
            acc[g * 4 + 1] = fmaf(qv, kvv.y, acc[g * 4 + 1]);
            acc[g * 4 + 2] = fmaf(qv, kvv.z, acc[g * 4 + 2]);
            acc[g * 4 + 3] = fmaf(qv, kvv.w, acc[g * 4 + 3]);
        }
    }
    float* orow = o + (long)(b * Nc + i) * Dc + h * 64 + e0;
    #pragma unroll
    for (int g = 0; g < 8; g++)
        *(float4*)&orow[g * 4] = *(float4*)&acc[g * 4];
}

// --------------------------------- host ------------------------------------
static inline int cdiv(int a, int b) { return (a + b - 1) / b; }

extern "C" void kernel_launch(void* const* d_in, const int* in_sizes, int n_in,
                              void* d_out, int out_size) {
    (void)in_sizes; (void)n_in; (void)out_size;
    const float* in_x  = (const float*)d_in[0];
    const float* in_h  = (const float*)d_in[1];
    const float* in_sp = (const float*)d_in[2];
    const float* in_tp = (const float*)d_in[3];

    float *pos, *X, *Y, *h, *hn, *xnall, *qkvpre, *qkv, *kvp, *o, *x2, *ln2, *t1;
    cudaGetSymbolAddress((void**)&pos,    g_pos);
    cudaGetSymbolAddress((void**)&X,      g_x);
    cudaGetSymbolAddress((void**)&Y,      g_y);
    cudaGetSymbolAddress((void**)&h,      g_h);
    cudaGetSymbolAddress((void**)&hn,     g_hn);
    cudaGetSymbolAddress((void**)&xnall,  g_xnall);
    cudaGetSymbolAddress((void**)&qkvpre, g_qkvpre);
    cudaGetSymbolAddress((void**)&qkv,    g_qkv);
    cudaGetSymbolAddress((void**)&kvp,    g_kvp);
    cudaGetSymbolAddress((void**)&o,      g_o);
    cudaGetSymbolAddress((void**)&x2,     g_x2);
    cudaGetSymbolAddress((void**)&ln2,    g_ln2);
    cudaGetSymbolAddress((void**)&t1,     g_t1);
    float* out = (float*)d_out;

    pos_kernel<<<cdiv(TOTc, 256), 256>>>(in_tp, in_sp, pos);
    vadd_kernel<<<cdiv(TOTc, 256), 256>>>(in_x, pos, X, TOTc);

    for (int layer = 0; layer < 2; layer++) {
        float* ybase = (layer == 0) ? Y : out;
        for (int dir = 0; dir < 2; dir++) {
            int s4 = dir * 2 + layer;
            const float* lnig  = (const float*)d_in[4]  + (long)s4 * Dc;
            const float* lnib  = (const float*)d_in[5]  + (long)s4 * Dc;
            const float* lnhg  = (const float*)d_in[6]  + (long)s4 * Dc;
            const float* lnhb  = (const float*)d_in[7]  + (long)s4 * Dc;
            const float* lnog  = (const float*)d_in[8]  + (long)s4 * Dc;
            const float* lnob  = (const float*)d_in[9]  + (long)s4 * Dc;
            const float* Wqkv  = (const float*)d_in[10] + (long)s4 * Dc * D3c;
            const float* bqkv  = (const float*)d_in[11] + (long)s4 * D3c;
            const float* Wqkvh = (const float*)d_in[12] + (long)s4 * Dc * D3c;
            const float* bqkvh = (const float*)d_in[13] + (long)s4 * D3c;
            const float* Wout  = (const float*)d_in[14] + (long)s4 * Dc * Dc;
            const float* bout  = (const float*)d_in[15] + (long)s4 * Dc;
            const float* W1    = (const float*)d_in[16] + (long)s4 * Dc * Mc;
            const float* b1    = (const float*)d_in[17] + (long)s4 * Mc;
            const float* W2    = (const float*)d_in[18] + (long)s4 * Mc * Dc;
            const float* b2    = (const float*)d_in[19] + (long)s4 * Dc;

            // batched loop-invariant half: xn_all, pre = xn_all@Wqkv + bqkv
            ln_xall<<<BLNc, 256>>>(X, lnig, lnib, xnall);
            {
                EpiAux a = {};
                tgemm<0><<<dim3(D3c / 64, BLNc / 128), 128>>>(
                    xnall, Dc, Wqkv, D3c, bqkv, qkvpre, D3c, Dc, a);
            }

            copy_kernel<<<cdiv(BNDc, 256), 256>>>(in_h, h, BNDc);

            for (int ss = 0; ss < Lc; ss++) {
                int t  = (dir == 0) ? ss : (Lc - 1 - ss);
                int tp = (dir == 0) ? layer : t;   // ref quirk: fwd uses pos[:, layer]
                int xoff = t * NDc;
                int tpoff = tp * NDc;

                ln_step<<<BNc, 256>>>(h, NDc, 0, pos, LNDc, tpoff, lnhg, lnhb, hn);

                EpiAux a2 = {};
                a2.pre = qkvpre + (long)t * BNc * D3c;
                tgemm<2><<<dim3(D3c / 64, BNc / 128), 128>>>(
                    hn, Dc, Wqkvh, D3c, bqkvh, qkv, D3c, Dc, a2);

                kv_partial_kernel<<<Bc * Hc * 8, 256>>>(qkv, kvp);
                o_kernel<<<Bc * Hc * 8, 256>>>(qkv, kvp, o);

                EpiAux a3 = {};
                a3.X = X; a3.xoff = xoff; a3.h = h; a3.pos = pos;
                a3.tpoff = tpoff; a3.x2w = x2;
                tgemm<3><<<dim3(Dc / 64, BNc / 128), 128>>>(
                    o, Dc, Wout, Dc, bout, x2, Dc, Dc, a3);

                ln_step<<<BNc, 256>>>(x2, NDc, 0, nullptr, 0, 0, lnog, lnob, ln2);

                tgemm<1><<<dim3(Mc / 64, BNc / 128), 128>>>(
                    ln2, Dc, W1, Mc, b1, t1, Mc, Dc, EpiAux{});

                EpiAux a4 = {};
                a4.x2r = x2; a4.y = ybase; a4.yoff = xoff; a4.add = dir;
                tgemm<4><<<dim3(Dc / 64, BNc / 128), 128>>>(
                    t1, Mc, W2, Dc, b2, t1, Dc, Mc, a4);
            }
        }
        if (layer == 0)
            vadd_kernel<<<cdiv(TOTc, 256), 256>>>(Y, pos, X, TOTc);
    }
}

// round 14
// speedup vs baseline: 1.8043x; 1.8043x over previous
#include <cuda_runtime.h>
#include <cuda_bf16.h>
#include <math.h>
#include <stdint.h>

// ---------------------------------------------------------------------------
// GPTrack2D encoder — tf32 mma.sync (m16n8k8), pre-converted tf32 operands
// (no in-loop CVT), 64x64 warp tiles (BM=128,BN=128), merged fwd/bwd
// directions (M=4096 sequential GEMMs), cp.async double buffer.
// R13 fix: yf/yb were separate __device__ symbols but EPI4 indexed them as
// contiguous (y + dir*TOTc) -> illegal memory access. Now one g_y2[2*TOTc].
// NOTE: tcgen05 does NOT compile in this harness (ptxas target sm_103).
// ---------------------------------------------------------------------------

#define Bc 2
#define Lc 12
#define Nc 1024
#define Dc 768
#define Hc 12
#define Mc 3072
#define D3c 2304
#define BNc (Bc*Nc)          /* 2048 */
#define BLNc (Bc*Lc*Nc)      /* 24576 */
#define NDc (Nc*Dc)
#define LNDc (Lc*Nc*Dc)
#define TOTc (Bc*Lc*Nc*Dc)
#define BNDc (Bc*Nc*Dc)

// ------------------------- device scratch (no allocs) ----------------------
__device__ float    g_pos   [TOTc];
__device__ float    g_x     [TOTc];
__device__ float    g_y2    [2l*TOTc];   // [0]=yf, [TOTc]=yb — CONTIGUOUS
__device__ float    g_h     [2*BNDc];
__device__ float    g_qkvpre[2l*BLNc*D3c];
__device__ float    g_qkv   [2*BNc*D3c];
__device__ float    g_kvp   [2*Bc*Hc*8*64*64];
__device__ float    g_x2    [2*BNDc];
// tf32-bit-pattern (u32) activations
__device__ unsigned g_xnall [2*BLNc*Dc];
__device__ unsigned g_hn    [2*BNDc];
__device__ unsigned g_ln2   [2*BNDc];
__device__ unsigned g_o     [2*BNDc];
__device__ unsigned g_t1    [2*BNc*Mc];
// tf32 weights (same [s4][K][N] layout as inputs, just converted)
__device__ unsigned g_Wqkv  [4*Dc*D3c];
__device__ unsigned g_Wqkvh [4*Dc*D3c];
__device__ unsigned g_Wout  [4*Dc*Dc];
__device__ unsigned g_W1    [4*Dc*Mc];
__device__ unsigned g_W2    [4*Mc*Dc];

__device__ __forceinline__ float gelu_f(float x) {
    return 0.5f * x * (1.0f + erff(x * 0.70710678118654752440f));
}
__device__ __forceinline__ unsigned f2tf32(float x) {
    unsigned r;
    asm("cvt.rna.tf32.f32 %0, %1;" : "=r"(r) : "f"(x));
    return r;
}
__device__ __forceinline__ void mma_tf32(float c[4], unsigned a0, unsigned a1,
                                         unsigned a2, unsigned a3,
                                         unsigned b0, unsigned b1) {
    asm volatile(
        "mma.sync.aligned.m16n8k8.row.col.f32.tf32.tf32.f32 "
        "{%0,%1,%2,%3},{%4,%5,%6,%7},{%8,%9},{%0,%1,%2,%3};"
        : "+f"(c[0]), "+f"(c[1]), "+f"(c[2]), "+f"(c[3])
        : "r"(a0), "r"(a1), "r"(a2), "r"(a3), "r"(b0), "r"(b1));
}
__device__ __forceinline__ void cp16(void* sdst, const void* gsrc) {
    unsigned s = (unsigned)__cvta_generic_to_shared(sdst);
    asm volatile("cp.async.cg.shared.global [%0], [%1], 16;" :: "r"(s), "l"(gsrc));
}

// ------------------------------- elementwise -------------------------------
__global__ void pos_kernel(const float* __restrict__ tpos,
                           const float* __restrict__ spos,
                           float* __restrict__ pos) {
    int idx = blockIdx.x * blockDim.x + threadIdx.x;
    if (idx >= TOTc) return;
    int d = idx % Dc;
    int n = (idx / Dc) % Nc;
    int l = (idx / NDc) % Lc;
    int b = idx / LNDc;
    pos[idx] = tpos[(b * Lc + l) * Dc + d] * spos[(b * Nc + n) * Dc + d];
}
__global__ void vadd_kernel(const float* __restrict__ a,
                            const float* __restrict__ b,
                            float* __restrict__ c, int n) {
    int idx = blockIdx.x * blockDim.x + threadIdx.x;
    if (idx < n) c[idx] = a[idx] + b[idx];
}
// layer-end combine: dst = yf + yb (+pos if pos!=null)
__global__ void combine_kernel(const float* __restrict__ yf,
                               const float* __restrict__ yb,
                               const float* __restrict__ pos,
                               float* __restrict__ dst, int n) {
    int idx = blockIdx.x * blockDim.x + threadIdx.x;
    if (idx < n) {
        float v = yf[idx] + yb[idx];
        if (pos) v += pos[idx];
        dst[idx] = v;
    }
}
// h[0]=h[1]=src
__global__ void hinit_kernel(const float* __restrict__ src,
                             float* __restrict__ h) {
    int idx = blockIdx.x * blockDim.x + threadIdx.x;
    if (idx < BNDc) { h[idx] = src[idx]; h[idx + BNDc] = src[idx]; }
}
// weight fp32 -> tf32 bits
__global__ void wconv_kernel(const float* __restrict__ in,
                             unsigned* __restrict__ out, long n) {
    long idx = (long)blockIdx.x * blockDim.x + threadIdx.x;
    if (idx < n) out[idx] = f2tf32(in[idx]);
}

// ------------------------------- layernorm ---------------------------------
__device__ __forceinline__ void ln_row(float v0, float v1, float v2,
                                       const float* __restrict__ gam,
                                       const float* __restrict__ bet,
                                       unsigned* __restrict__ dp, int t,
                                       float* red) {
    float s = v0 + v1 + v2;
    #pragma unroll
    for (int o = 16; o > 0; o >>= 1) s += __shfl_down_sync(0xffffffffu, s, o);
    if ((t & 31) == 0) red[t >> 5] = s;
    __syncthreads();
    if (t < 32) {
        float x = (t < 8) ? red[t] : 0.0f;
        #pragma unroll
        for (int o = 4; o > 0; o >>= 1) x += __shfl_down_sync(0xffffffffu, x, o);
        if (t == 0) red[0] = x;
    }
    __syncthreads();
    float m = red[0] * (1.0f / 768.0f);
    __syncthreads();
    float d0 = v0 - m, d1 = v1 - m, d2 = v2 - m;
    float q2 = d0 * d0 + d1 * d1 + d2 * d2;
    #pragma unroll
    for (int o = 16; o > 0; o >>= 1) q2 += __shfl_down_sync(0xffffffffu, q2, o);
    if ((t & 31) == 0) red[t >> 5] = q2;
    __syncthreads();
    if (t < 32) {
        float x = (t < 8) ? red[t] : 0.0f;
        #pragma unroll
        for (int o = 4; o > 0; o >>= 1) x += __shfl_down_sync(0xffffffffu, x, o);
        if (t == 0) red[0] = x;
    }
    __syncthreads();
    float r = rsqrtf(red[0] * (1.0f / 768.0f) + 1e-5f);
    dp[t]       = f2tf32(d0 * r * gam[t]       + bet[t]);
    dp[t + 256] = f2tf32(d1 * r * gam[t + 256] + bet[t + 256]);
    dp[t + 512] = f2tf32(d2 * r * gam[t + 512] + bet[t + 512]);
}

// merged-dir batched LN over all timesteps: grid = 2*BLNc
__global__ void ln_xall_m(const float* __restrict__ X,
                          const float* __restrict__ gbase,
                          const float* __restrict__ bbase,
                          unsigned* __restrict__ dst) {
    __shared__ float red[32];
    int R = blockIdx.x;
    int z = R / BLNc;
    int R2 = R - z * BLNc;
    int tt = R2 / BNc;
    int rr = R2 - tt * BNc;
    int b = rr >> 10, n = rr & 1023;
    const float* p = X + (long)b * LNDc + (long)tt * NDc + (long)n * Dc;
    const float* gam = gbase + (long)z * 2 * Dc;
    const float* bet = bbase + (long)z * 2 * Dc;
    int t = threadIdx.x;
    ln_row(p[t], p[t + 256], p[t + 512], gam, bet, dst + (long)R * Dc, t, red);
}

// merged-dir hn = LN(h + pos[:,tp_z]) : grid 4096
__global__ void ln_h_m(const float* __restrict__ h,
                       const float* __restrict__ pos, int tp0, int tp1,
                       const float* __restrict__ gbase,
                       const float* __restrict__ bbase,
                       unsigned* __restrict__ dst) {
    __shared__ float red[32];
    int row = blockIdx.x;
    int z = row >> 11;
    int lrow = row & 2047;
    int b = lrow >> 10, n = lrow & 1023;
    const float* p = h + (long)row * Dc;
    int tp = z ? tp1 : tp0;
    const float* q = pos + (long)b * LNDc + (long)tp * NDc + (long)n * Dc;
    const float* gam = gbase + (long)z * 2 * Dc;
    const float* bet = bbase + (long)z * 2 * Dc;
    int t = threadIdx.x;
    ln_row(p[t] + q[t], p[t + 256] + q[t + 256], p[t + 512] + q[t + 512],
           gam, bet, dst + (long)row * Dc, t, red);
}

// merged-dir ln2 = LN(x2) : grid 4096
__global__ void ln2_m(const float* __restrict__ x2,
                      const float* __restrict__ gbase,
                      const float* __restrict__ bbase,
                      unsigned* __restrict__ dst) {
    __shared__ float red[32];
    int row = blockIdx.x;
    int z = row >> 11;
    const float* p = x2 + (long)row * Dc;
    const float* gam = gbase + (long)z * 2 * Dc;
    const float* bet = bbase + (long)z * 2 * Dc;
    int t = threadIdx.x;
    ln_row(p[t], p[t + 256], p[t + 512], gam, bet, dst + (long)row * Dc, t, red);
}

// ----------------------------- tf32 MMA GEMM -------------------------------
// C[Mtot,N] = A[Mtot,K] @ B_dir[K,N] + bias_dir, dir = row/Mper (2 dirs).
// BM=128, BN=128, BK=16, 128 threads, 4 warps of 64x64, double buffer.
// Operands are pre-converted tf32 bit patterns; inner loop is LDS+MMA only.
struct EpiAux {
    const float* pre; int t0, t1;  // EPI2 (+ EPI3/4 reuse t0/t1)
    const float* X;                // EPI3
    float* h;                      // EPI3 [2*BNDc]
    const float* pos; int tp0, tp1;// EPI3
    float* x2w;                    // EPI3 [2*BNDc]
    const float* x2r;              // EPI4
    float* y;                      // EPI4 [2*TOTc] contiguous (yf | yb)
    unsigned* t1o;                 // EPI1
};

template<int EPI>
__global__ void __launch_bounds__(128)
tgemm(const unsigned* __restrict__ A, int lda,
      const unsigned* __restrict__ B, long bzstr, int ldb,
      const float* __restrict__ bias, long bizstr,
      float* __restrict__ C, int N, int K, int Mper, EpiAux aux) {
    __shared__ unsigned As[2][128][20];
    __shared__ unsigned Bs[2][16][136];

    const int tid = threadIdx.x;
    const int lane = tid & 31;
    const int wid = tid >> 5;
    const int warp_m = (wid >> 1) * 64;
    const int warp_n = (wid & 1) * 64;
    const int bx = blockIdx.x, by = blockIdx.y;
    const int r = lane >> 2, cq = lane & 3;
    const int row0 = by * 128;
    const int dir = (row0 >= Mper) ? 1 : 0;
    const unsigned* Bd = B + (long)dir * bzstr;
    const float* biasd = bias + (long)dir * bizstr;

    float acc[4][8][4];
    #pragma unroll
    for (int i = 0; i < 4; i++)
        #pragma unroll
        for (int j = 0; j < 8; j++)
            #pragma unroll
            for (int q = 0; q < 4; q++) acc[i][j][q] = 0.0f;

    const int S = K / 16;

    auto issue_stage = [&](int s) {
        int st = s & 1;
        int k0 = s * 16;
        #pragma unroll
        for (int i = 0; i < 4; i++) {                 // A: 512 uint4 slots
            int lid = tid + i * 128;
            int am = lid >> 2, ak = (lid & 3) * 4;
            cp16(&As[st][am][ak], A + (long)(row0 + am) * lda + k0 + ak);
        }
        #pragma unroll
        for (int i = 0; i < 4; i++) {                 // B: 512 uint4 slots
            int lid = tid + i * 128;
            int br = lid >> 5, bc = (lid & 31) * 4;
            cp16(&Bs[st][br][bc], Bd + (long)(k0 + br) * ldb + bx * 128 + bc);
        }
    };

    issue_stage(0);
    asm volatile("cp.async.commit_group;");

    for (int s = 0; s < S; s++) {
        if (s + 1 < S) {
            issue_stage(s + 1);
            asm volatile("cp.async.commit_group;");
            asm volatile("cp.async.wait_group 1;");
        } else {
            asm volatile("cp.async.wait_group 0;");
        }
        __syncthreads();
        const int buf = s & 1;
        #pragma unroll
        for (int ka = 0; ka < 2; ka++) {
            const int kb = ka * 8;
            unsigned af[4][4], bf[8][2];
            #pragma unroll
            for (int mi = 0; mi < 4; mi++) {
                int m0 = warp_m + mi * 16 + r;
                af[mi][0] = As[buf][m0][kb + cq];
                af[mi][1] = As[buf][m0 + 8][kb + cq];
                af[mi][2] = As[buf][m0][kb + cq + 4];
                af[mi][3] = As[buf][m0 + 8][kb + cq + 4];
            }
            #pragma unroll
            for (int ni = 0; ni < 8; ni++) {
                int n0 = warp_n + ni * 8 + r;
                bf[ni][0] = Bs[buf][kb + cq][n0];
                bf[ni][1] = Bs[buf][kb + cq + 4][n0];
            }
            #pragma unroll
            for (int mi = 0; mi < 4; mi++)
                #pragma unroll
                for (int ni = 0; ni < 8; ni++)
                    mma_tf32(acc[mi][ni], af[mi][0], af[mi][1], af[mi][2],
                             af[mi][3], bf[ni][0], bf[ni][1]);
        }
        __syncthreads();
    }

    // ---- epilogue ----
    const int t_z  = dir ? aux.t1 : aux.t0;
    const int tp_z = dir ? aux.tp1 : aux.tp0;
    #pragma unroll
    for (int mi = 0; mi < 4; mi++) {
        #pragma unroll
        for (int ni = 0; ni < 8; ni++) {
            int col = bx * 128 + warp_n + ni * 8 + 2 * cq;
            float bs0 = biasd[col], bs1 = biasd[col + 1];
            #pragma unroll
            for (int half = 0; half < 2; half++) {
                int row = row0 + warp_m + mi * 16 + r + half * 8;
                float v0 = acc[mi][ni][half * 2 + 0] + bs0;
                float v1 = acc[mi][ni][half * 2 + 1] + bs1;
                if (EPI == 0) {
                    float* cp = C + (long)row * N + col;
                    cp[0] = v0; cp[1] = v1;
                } else if (EPI == 1) {
                    unsigned* tp = aux.t1o + (long)row * N + col;
                    tp[0] = f2tf32(gelu_f(v0));
                    tp[1] = f2tf32(gelu_f(v1));
                } else if (EPI == 2) {
                    int lrow = row - dir * 2048;
                    const float* pp = aux.pre
                        + ((long)dir * Lc + t_z) * BNc * D3c
                        + (long)lrow * D3c + col;
                    v0 += pp[0]; v1 += pp[1];
                    if (col < 1536)     v0 = (v0 > 0.f) ? v0 + 1.f : expf(v0);
                    if (col + 1 < 1536) v1 = (v1 > 0.f) ? v1 + 1.f : expf(v1);
                    float* cp = C + (long)row * N + col;
                    cp[0] = v0; cp[1] = v1;
                } else if (EPI == 3) {
                    int lrow = row & 2047;
                    int b = lrow >> 10, rr = lrow & 1023;
                    long xb = (long)b * LNDc + (long)t_z * NDc + (long)rr * Dc + col;
                    long pb = (long)b * LNDc + (long)tp_z * NDc + (long)rr * Dc + col;
                    long idx = (long)row * Dc + col;
                    aux.x2w[idx]     = v0 + aux.X[xb];
                    aux.x2w[idx + 1] = v1 + aux.X[xb + 1];
                    aux.h[idx]     = v0 + aux.h[idx]     + aux.pos[pb];
                    aux.h[idx + 1] = v1 + aux.h[idx + 1] + aux.pos[pb + 1];
                } else if (EPI == 4) {
                    int lrow = row & 2047;
                    int b = lrow >> 10, rr = lrow & 1023;
                    long idx = (long)row * Dc + col;
                    float w0 = v0 + aux.x2r[idx];
                    float w1 = v1 + aux.x2r[idx + 1];
                    long yo = (long)dir * TOTc + (long)b * LNDc
                            + (long)t_z * NDc + (long)rr * Dc + col;
                    aux.y[yo] = w0; aux.y[yo + 1] = w1;
                }
            }
        }
    }
}

// ----------------------- linear-attention small GEMMs ----------------------
__global__ void kv_partial_m(const float* __restrict__ qkvg,
                             float* __restrict__ kvpg) {
    int z = blockIdx.y;
    const float* qkv = qkvg + (long)z * BNc * D3c;
    float* kvp = kvpg + (long)z * Bc * Hc * 8 * 4096;
    int chunk = blockIdx.x & 7;
    int bh = blockIdx.x >> 3;
    int h = bh % Hc, b = bh / Hc;
    int t = threadIdx.x;
    __shared__ float ks[8][64], vs[8][64];
    int d0 = (t & 15) * 4, e0 = (t >> 4) * 4;
    float acc[4][4];
    #pragma unroll
    for (int i = 0; i < 4; i++)
        #pragma unroll
        for (int j = 0; j < 4; j++) acc[i][j] = 0.0f;
    int j0 = chunk * 128;
    const float* kbase = qkv + (long)(b * Nc) * D3c + Dc + h * 64;
    const float* vbase = kbase + Dc;
    for (int js = 0; js < 128; js += 8) {
        #pragma unroll
        for (int rr = 0; rr < 2; rr++) {
            int id = t + rr * 256;
            int jj = id >> 6, dd = id & 63;
            long roff = (long)(j0 + js + jj) * D3c + dd;
            ks[jj][dd] = kbase[roff];
            vs[jj][dd] = vbase[roff];
        }
        __syncthreads();
        #pragma unroll
        for (int jj = 0; jj < 8; jj++) {
            float kd[4], ve[4];
            *(float4*)kd = *(const float4*)&ks[jj][d0];
            *(float4*)ve = *(const float4*)&vs[jj][e0];
            #pragma unroll
            for (int i = 0; i < 4; i++)
                #pragma unroll
                for (int j = 0; j < 4; j++)
                    acc[i][j] = fmaf(kd[i], ve[j], acc[i][j]);
        }
        __syncthreads();
    }
    float* dst = kvp + ((long)bh * 8 + chunk) * 4096;
    #pragma unroll
    for (int i = 0; i < 4; i++)
        #pragma unroll
        for (int j = 0; j < 4; j++)
            dst[(d0 + i) * 64 + e0 + j] = acc[i][j];
}

__global__ void o_kernel_m(const float* __restrict__ qkvg,
                           const float* __restrict__ kvpg,
                           unsigned* __restrict__ og) {
    int z = blockIdx.y;
    const float* qkv = qkvg + (long)z * BNc * D3c;
    const float* kvp = kvpg + (long)z * Bc * Hc * 8 * 4096;
    unsigned* o = og + (long)z * BNDc;
    int ic = blockIdx.x & 7;
    int bh = blockIdx.x >> 3;
    int h = bh % Hc, b = bh / Hc;
    int t = threadIdx.x;
    __shared__ float kvs[4096];
    const float* src = kvp + (long)bh * 8 * 4096;
    for (int x = t; x < 4096; x += 256) {
        float s = 0.0f;
        #pragma unroll
        for (int c = 0; c < 8; c++) s += src[c * 4096 + x];
        kvs[x] = s;
    }
    __syncthreads();
    int i = ic * 128 + (t >> 1);
    int e0 = (t & 1) * 32;
    const float* qrow = qkv + (long)(b * Nc + i) * D3c + h * 64;
    float acc[32];
    #pragma unroll
    for (int g = 0; g < 32; g++) acc[g] = 0.0f;
    #pragma unroll 4
    for (int d = 0; d < 64; d++) {
        float qv = qrow[d];
        #pragma unroll
        for (int g = 0; g < 8; g++) {
            float4 kvv = *(const float4*)&kvs[d * 64 + e0 + g * 4];
            acc[g * 4 + 0] = fmaf(qv, kvv.x, acc[g * 4 + 0]);
            acc[g * 4 + 1] = fmaf(qv, kvv.y, acc[g * 4 + 1]);
            acc[g * 4 + 2] = fmaf(qv, kvv.z, acc[g * 4 + 2]);
            acc[g * 4 + 3] = fmaf(qv, kvv.w, acc[g * 4 + 3]);
        }
    }
    long ob = (long)(b * Nc + i) * Dc + h * 64 + e0;
    #pragma unroll
    for (int g = 0; g < 32; g++) o[ob + g] = f2tf32(acc[g]);
}

// --------------------------------- host ------------------------------------
static inline int cdiv(int a, int b) { return (a + b - 1) / b; }

extern "C" void kernel_launch(void* const* d_in, const int* in_sizes, int n_in,
                              void* d_out, int out_size) {
    (void)in_sizes; (void)n_in; (void)out_size;
    const float* in_x  = (const float*)d_in[0];
    const float* in_h  = (const float*)d_in[1];
    const float* in_sp = (const float*)d_in[2];
    const float* in_tp = (const float*)d_in[3];

    float *pos, *X, *y2, *h, *qkvpre, *qkv, *kvp, *x2;
    unsigned *xnall, *hn, *ln2, *o, *t1;
    unsigned *wq, *wqh, *wo, *w1, *w2;
    cudaGetSymbolAddress((void**)&pos,    g_pos);
    cudaGetSymbolAddress((void**)&X,      g_x);
    cudaGetSymbolAddress((void**)&y2,     g_y2);
    cudaGetSymbolAddress((void**)&h,      g_h);
    cudaGetSymbolAddress((void**)&qkvpre, g_qkvpre);
    cudaGetSymbolAddress((void**)&qkv,    g_qkv);
    cudaGetSymbolAddress((void**)&kvp,    g_kvp);
    cudaGetSymbolAddress((void**)&x2,     g_x2);
    cudaGetSymbolAddress((void**)&xnall,  g_xnall);
    cudaGetSymbolAddress((void**)&hn,     g_hn);
    cudaGetSymbolAddress((void**)&ln2,    g_ln2);
    cudaGetSymbolAddress((void**)&o,      g_o);
    cudaGetSymbolAddress((void**)&t1,     g_t1);
    cudaGetSymbolAddress((void**)&wq,     g_Wqkv);
    cudaGetSymbolAddress((void**)&wqh,    g_Wqkvh);
    cudaGetSymbolAddress((void**)&wo,     g_Wout);
    cudaGetSymbolAddress((void**)&w1,     g_W1);
    cudaGetSymbolAddress((void**)&w2,     g_W2);
    float* out = (float*)d_out;
    float* yf = y2;
    float* yb = y2 + (long)TOTc;

    // prologue
    pos_kernel<<<cdiv(TOTc, 256), 256>>>(in_tp, in_sp, pos);
    vadd_kernel<<<cdiv(TOTc, 256), 256>>>(in_x, pos, X, TOTc);
    wconv_kernel<<<cdiv(4 * Dc * D3c, 256), 256>>>((const float*)d_in[10], wq,  4l * Dc * D3c);
    wconv_kernel<<<cdiv(4 * Dc * D3c, 256), 256>>>((const float*)d_in[12], wqh, 4l * Dc * D3c);
    wconv_kernel<<<cdiv(4 * Dc * Dc,  256), 256>>>((const float*)d_in[14], wo,  4l * Dc * Dc);
    wconv_kernel<<<cdiv(4 * Dc * Mc,  256), 256>>>((const float*)d_in[16], w1,  4l * Dc * Mc);
    wconv_kernel<<<cdiv(4 * Mc * Dc,  256), 256>>>((const float*)d_in[18], w2,  4l * Mc * Dc);

    const long WQZ = 2l * Dc * D3c;   // dir stride in s4 units (s4 = dir*2+layer)
    const long WOZ = 2l * Dc * Dc;
    const long W1Z = 2l * Dc * Mc;
    const long W2Z = 2l * Mc * Dc;

    for (int layer = 0; layer < 2; layer++) {
        const float* lnig = (const float*)d_in[4] + (long)layer * Dc;
        const float* lnib = (const float*)d_in[5] + (long)layer * Dc;
        const float* lnhg = (const float*)d_in[6] + (long)layer * Dc;
        const float* lnhb = (const float*)d_in[7] + (long)layer * Dc;
        const float* lnog = (const float*)d_in[8] + (long)layer * Dc;
        const float* lnob = (const float*)d_in[9] + (long)layer * Dc;
        const float* bqkv  = (const float*)d_in[11] + (long)layer * D3c;
        const float* bqkvh = (const float*)d_in[13] + (long)layer * D3c;
        const float* bout  = (const float*)d_in[15] + (long)layer * Dc;
        const float* b1    = (const float*)d_in[17] + (long)layer * Mc;
        const float* b2    = (const float*)d_in[19] + (long)layer * Dc;
        const unsigned* Wq  = wq  + (long)layer * Dc * D3c;
        const unsigned* Wqh = wqh + (long)layer * Dc * D3c;
        const unsigned* Wo  = wo  + (long)layer * Dc * Dc;
        const unsigned* W1p = w1  + (long)layer * Dc * Mc;
        const unsigned* W2p = w2  + (long)layer * Mc * Dc;

        // batched loop-invariant half, both dirs: pre = LN(x_t)@Wqkv + bqkv
        ln_xall_m<<<2 * BLNc, 256>>>(X, lnig, lnib, xnall);
        {
            EpiAux a = {};
            tgemm<0><<<dim3(D3c / 128, 2 * BLNc / 128), 128>>>(
                xnall, Dc, Wq, WQZ, D3c, bqkv, 2 * D3c,
                qkvpre, D3c, Dc, BLNc, a);
        }
        hinit_kernel<<<cdiv(BNDc, 256), 256>>>(in_h, h);

        for (int ss = 0; ss < Lc; ss++) {
            int t0 = ss, t1s = Lc - 1 - ss;
            int tp0 = layer, tp1 = t1s;   // ref quirk: fwd uses pos[:, layer]

            ln_h_m<<<2 * BNc, 256>>>(h, pos, tp0, tp1, lnhg, lnhb, hn);

            EpiAux a2 = {};
            a2.pre = qkvpre; a2.t0 = t0; a2.t1 = t1s;
            tgemm<2><<<dim3(D3c / 128, 2 * BNc / 128), 128>>>(
                hn, Dc, Wqh, WQZ, D3c, bqkvh, 2 * D3c,
                qkv, D3c, Dc, BNc, a2);

            kv_partial_m<<<dim3(Bc * Hc * 8, 2), 256>>>(qkv, kvp);
            o_kernel_m<<<dim3(Bc * Hc * 8, 2), 256>>>(qkv, kvp, o);

            EpiAux a3 = {};
            a3.t0 = t0; a3.t1 = t1s; a3.X = X; a3.h = h;
            a3.pos = pos; a3.tp0 = tp0; a3.tp1 = tp1; a3.x2w = x2;
            tgemm<3><<<dim3(Dc / 128, 2 * BNc / 128), 128>>>(
                o, Dc, Wo, WOZ, Dc, bout, 2 * Dc,
                x2, Dc, Dc, BNc, a3);

            ln2_m<<<2 * BNc, 256>>>(x2, lnog, lnob, ln2);

            EpiAux a1 = {};
            a1.t1o = t1;
            tgemm<1><<<dim3(Mc / 128, 2 * BNc / 128), 128>>>(
                ln2, Dc, W1p, W1Z, Mc, b1, 2 * Mc,
                nullptr, Mc, Dc, BNc, a1);

            EpiAux a4 = {};
            a4.t0 = t0; a4.t1 = t1s; a4.x2r = x2; a4.y = y2;  // contiguous yf|yb
            tgemm<4><<<dim3(Dc / 128, 2 * BNc / 128), 128>>>(
                t1, Mc, W2p, W2Z, Dc, b2, 2 * Dc,
                nullptr, Dc, Mc, BNc, a4);
        }

        if (layer == 0)
            combine_kernel<<<cdiv(TOTc, 256), 256>>>(yf, yb, pos, X, TOTc);
        else
            combine_kernel<<<cdiv(TOTc, 256), 256>>>(yf, yb, nullptr, out, TOTc);
    }
}

// round 15
// speedup vs baseline: 1.9554x; 1.0838x over previous
#include <cuda_runtime.h>
#include <cuda_bf16.h>
#include <math.h>
#include <stdint.h>

// ---------------------------------------------------------------------------
// GPTrack2D encoder — tf32 mma.sync (m16n8k8), pre-converted tf32 operands,
// 64x64 warp tiles (BM=128,BN=128), merged fwd/bwd directions, and (R14)
// BK=32 with a 3-stage cp.async pipeline in dynamic smem: half the
// iterations/syncs, 2-stage lookahead. Accumulation order unchanged.
// ---------------------------------------------------------------------------

#define Bc 2
#define Lc 12
#define Nc 1024
#define Dc 768
#define Hc 12
#define Mc 3072
#define D3c 2304
#define BNc (Bc*Nc)          /* 2048 */
#define BLNc (Bc*Lc*Nc)      /* 24576 */
#define NDc (Nc*Dc)
#define LNDc (Lc*Nc*Dc)
#define TOTc (Bc*Lc*Nc*Dc)
#define BNDc (Bc*Nc*Dc)

// ------------------------- device scratch (no allocs) ----------------------
__device__ float    g_pos   [TOTc];
__device__ float    g_x     [TOTc];
__device__ float    g_y2    [2l*TOTc];   // [0]=yf, [TOTc]=yb — contiguous
__device__ float    g_h     [2*BNDc];
__device__ float    g_qkvpre[2l*BLNc*D3c];
__device__ float    g_qkv   [2*BNc*D3c];
__device__ float    g_kvp   [2*Bc*Hc*8*64*64];
__device__ float    g_x2    [2*BNDc];
// tf32-bit-pattern (u32) activations
__device__ unsigned g_xnall [2*BLNc*Dc];
__device__ unsigned g_hn    [2*BNDc];
__device__ unsigned g_ln2   [2*BNDc];
__device__ unsigned g_o     [2*BNDc];
__device__ unsigned g_t1    [2*BNc*Mc];
// tf32 weights (same [s4][K][N] layout as inputs, just converted)
__device__ unsigned g_Wqkv  [4*Dc*D3c];
__device__ unsigned g_Wqkvh [4*Dc*D3c];
__device__ unsigned g_Wout  [4*Dc*Dc];
__device__ unsigned g_W1    [4*Dc*Mc];
__device__ unsigned g_W2    [4*Mc*Dc];

__device__ __forceinline__ float gelu_f(float x) {
    return 0.5f * x * (1.0f + erff(x * 0.70710678118654752440f));
}
__device__ __forceinline__ unsigned f2tf32(float x) {
    unsigned r;
    asm("cvt.rna.tf32.f32 %0, %1;" : "=r"(r) : "f"(x));
    return r;
}
__device__ __forceinline__ void mma_tf32(float c[4], unsigned a0, unsigned a1,
                                         unsigned a2, unsigned a3,
                                         unsigned b0, unsigned b1) {
    asm volatile(
        "mma.sync.aligned.m16n8k8.row.col.f32.tf32.tf32.f32 "
        "{%0,%1,%2,%3},{%4,%5,%6,%7},{%8,%9},{%0,%1,%2,%3};"
        : "+f"(c[0]), "+f"(c[1]), "+f"(c[2]), "+f"(c[3])
        : "r"(a0), "r"(a1), "r"(a2), "r"(a3), "r"(b0), "r"(b1));
}
__device__ __forceinline__ void cp16(unsigned* sdst, const void* gsrc) {
    unsigned s = (unsigned)__cvta_generic_to_shared(sdst);
    asm volatile("cp.async.cg.shared.global [%0], [%1], 16;" :: "r"(s), "l"(gsrc));
}

// ------------------------------- elementwise -------------------------------
__global__ void pos_kernel(const float* __restrict__ tpos,
                           const float* __restrict__ spos,
                           float* __restrict__ pos) {
    int idx = blockIdx.x * blockDim.x + threadIdx.x;
    if (idx >= TOTc) return;
    int d = idx % Dc;
    int n = (idx / Dc) % Nc;
    int l = (idx / NDc) % Lc;
    int b = idx / LNDc;
    pos[idx] = tpos[(b * Lc + l) * Dc + d] * spos[(b * Nc + n) * Dc + d];
}
__global__ void vadd_kernel(const float* __restrict__ a,
                            const float* __restrict__ b,
                            float* __restrict__ c, int n) {
    int idx = blockIdx.x * blockDim.x + threadIdx.x;
    if (idx < n) c[idx] = a[idx] + b[idx];
}
__global__ void combine_kernel(const float* __restrict__ yf,
                               const float* __restrict__ yb,
                               const float* __restrict__ pos,
                               float* __restrict__ dst, int n) {
    int idx = blockIdx.x * blockDim.x + threadIdx.x;
    if (idx < n) {
        float v = yf[idx] + yb[idx];
        if (pos) v += pos[idx];
        dst[idx] = v;
    }
}
__global__ void hinit_kernel(const float* __restrict__ src,
                             float* __restrict__ h) {
    int idx = blockIdx.x * blockDim.x + threadIdx.x;
    if (idx < BNDc) { h[idx] = src[idx]; h[idx + BNDc] = src[idx]; }
}
__global__ void wconv_kernel(const float* __restrict__ in,
                             unsigned* __restrict__ out, long n) {
    long idx = (long)blockIdx.x * blockDim.x + threadIdx.x;
    if (idx < n) out[idx] = f2tf32(in[idx]);
}

// ------------------------------- layernorm ---------------------------------
__device__ __forceinline__ void ln_row(float v0, float v1, float v2,
                                       const float* __restrict__ gam,
                                       const float* __restrict__ bet,
                                       unsigned* __restrict__ dp, int t,
                                       float* red) {
    float s = v0 + v1 + v2;
    #pragma unroll
    for (int o = 16; o > 0; o >>= 1) s += __shfl_down_sync(0xffffffffu, s, o);
    if ((t & 31) == 0) red[t >> 5] = s;
    __syncthreads();
    if (t < 32) {
        float x = (t < 8) ? red[t] : 0.0f;
        #pragma unroll
        for (int o = 4; o > 0; o >>= 1) x += __shfl_down_sync(0xffffffffu, x, o);
        if (t == 0) red[0] = x;
    }
    __syncthreads();
    float m = red[0] * (1.0f / 768.0f);
    __syncthreads();
    float d0 = v0 - m, d1 = v1 - m, d2 = v2 - m;
    float q2 = d0 * d0 + d1 * d1 + d2 * d2;
    #pragma unroll
    for (int o = 16; o > 0; o >>= 1) q2 += __shfl_down_sync(0xffffffffu, q2, o);
    if ((t & 31) == 0) red[t >> 5] = q2;
    __syncthreads();
    if (t < 32) {
        float x = (t < 8) ? red[t] : 0.0f;
        #pragma unroll
        for (int o = 4; o > 0; o >>= 1) x += __shfl_down_sync(0xffffffffu, x, o);
        if (t == 0) red[0] = x;
    }
    __syncthreads();
    float r = rsqrtf(red[0] * (1.0f / 768.0f) + 1e-5f);
    dp[t]       = f2tf32(d0 * r * gam[t]       + bet[t]);
    dp[t + 256] = f2tf32(d1 * r * gam[t + 256] + bet[t + 256]);
    dp[t + 512] = f2tf32(d2 * r * gam[t + 512] + bet[t + 512]);
}

__global__ void ln_xall_m(const float* __restrict__ X,
                          const float* __restrict__ gbase,
                          const float* __restrict__ bbase,
                          unsigned* __restrict__ dst) {
    __shared__ float red[32];
    int R = blockIdx.x;
    int z = R / BLNc;
    int R2 = R - z * BLNc;
    int tt = R2 / BNc;
    int rr = R2 - tt * BNc;
    int b = rr >> 10, n = rr & 1023;
    const float* p = X + (long)b * LNDc + (long)tt * NDc + (long)n * Dc;
    const float* gam = gbase + (long)z * 2 * Dc;
    const float* bet = bbase + (long)z * 2 * Dc;
    int t = threadIdx.x;
    ln_row(p[t], p[t + 256], p[t + 512], gam, bet, dst + (long)R * Dc, t, red);
}

__global__ void ln_h_m(const float* __restrict__ h,
                       const float* __restrict__ pos, int tp0, int tp1,
                       const float* __restrict__ gbase,
                       const float* __restrict__ bbase,
                       unsigned* __restrict__ dst) {
    __shared__ float red[32];
    int row = blockIdx.x;
    int z = row >> 11;
    int lrow = row & 2047;
    int b = lrow >> 10, n = lrow & 1023;
    const float* p = h + (long)row * Dc;
    int tp = z ? tp1 : tp0;
    const float* q = pos + (long)b * LNDc + (long)tp * NDc + (long)n * Dc;
    const float* gam = gbase + (long)z * 2 * Dc;
    const float* bet = bbase + (long)z * 2 * Dc;
    int t = threadIdx.x;
    ln_row(p[t] + q[t], p[t + 256] + q[t + 256], p[t + 512] + q[t + 512],
           gam, bet, dst + (long)row * Dc, t, red);
}

__global__ void ln2_m(const float* __restrict__ x2,
                      const float* __restrict__ gbase,
                      const float* __restrict__ bbase,
                      unsigned* __restrict__ dst) {
    __shared__ float red[32];
    int row = blockIdx.x;
    int z = row >> 11;
    const float* p = x2 + (long)row * Dc;
    const float* gam = gbase + (long)z * 2 * Dc;
    const float* bet = bbase + (long)z * 2 * Dc;
    int t = threadIdx.x;
    ln_row(p[t], p[t + 256], p[t + 512], gam, bet, dst + (long)row * Dc, t, red);
}

// ----------------------------- tf32 MMA GEMM -------------------------------
// C[Mtot,N] = A[Mtot,K] @ B_dir[K,N] + bias_dir, dir = row/Mper (2 dirs).
// BM=128, BN=128, BK=32, 128 threads (4 warps, 64x64 each), 3-stage cp.async
// pipeline in dynamic smem. Inner loop is LDS+MMA only (tf32 pre-converted).
struct EpiAux {
    const float* pre; int t0, t1;  // EPI2 (+ EPI3/4 reuse t0/t1)
    const float* X;                // EPI3
    float* h;                      // EPI3 [2*BNDc]
    const float* pos; int tp0, tp1;// EPI3
    float* x2w;                    // EPI3 [2*BNDc]
    const float* x2r;              // EPI4
    float* y;                      // EPI4 [2*TOTc] contiguous (yf | yb)
    unsigned* t1o;                 // EPI1
};

#define ASTR 36                    /* 32 + 4 pad: ≡4 mod 32, conflict-free */
#define BSTR 136                   /* 128 + 8 pad: ≡8 mod 32, conflict-free */
#define A_ST (128 * ASTR)          /* words per A stage = 4608 */
#define B_ST (32 * BSTR)           /* words per B stage = 4352 */
#define TG_SMEM (3 * (A_ST + B_ST) * 4)   /* 107,520 B */

template<int EPI>
__global__ void __launch_bounds__(128)
tgemm(const unsigned* __restrict__ A, int lda,
      const unsigned* __restrict__ B, long bzstr, int ldb,
      const float* __restrict__ bias, long bizstr,
      float* __restrict__ C, int N, int K, int Mper, EpiAux aux) {
    extern __shared__ unsigned smem[];
    unsigned* Asm = smem;                    // [3][128][ASTR]
    unsigned* Bsm = smem + 3 * A_ST;         // [3][32][BSTR]

    const int tid = threadIdx.x;
    const int lane = tid & 31;
    const int wid = tid >> 5;
    const int warp_m = (wid >> 1) * 64;
    const int warp_n = (wid & 1) * 64;
    const int bx = blockIdx.x, by = blockIdx.y;
    const int r = lane >> 2, cq = lane & 3;
    const int row0 = by * 128;
    const int dir = (row0 >= Mper) ? 1 : 0;
    const unsigned* Bd = B + (long)dir * bzstr;
    const float* biasd = bias + (long)dir * bizstr;

    float acc[4][8][4];
    #pragma unroll
    for (int i = 0; i < 4; i++)
        #pragma unroll
        for (int j = 0; j < 8; j++)
            #pragma unroll
            for (int q = 0; q < 4; q++) acc[i][j][q] = 0.0f;

    const int S = K / 32;

    auto issue_stage = [&](int s) {
        int st = s % 3;
        int k0 = s * 32;
        unsigned* Ad = Asm + st * A_ST;
        unsigned* Bs = Bsm + st * B_ST;
        #pragma unroll
        for (int i = 0; i < 8; i++) {                 // A: 1024 uint4 slots
            int lid = tid + i * 128;
            int am = lid >> 3, ak = (lid & 7) * 4;
            cp16(Ad + am * ASTR + ak, A + (long)(row0 + am) * lda + k0 + ak);
        }
        #pragma unroll
        for (int i = 0; i < 8; i++) {                 // B: 1024 uint4 slots
            int lid = tid + i * 128;
            int br = lid >> 5, bc = (lid & 31) * 4;
            cp16(Bs + br * BSTR + bc, Bd + (long)(k0 + br) * ldb + bx * 128 + bc);
        }
    };

    issue_stage(0);
    asm volatile("cp.async.commit_group;");
    issue_stage(1);
    asm volatile("cp.async.commit_group;");

    for (int s = 0; s < S; s++) {
        if (s + 2 < S) {
            issue_stage(s + 2);
            asm volatile("cp.async.commit_group;");
            asm volatile("cp.async.wait_group 2;");
        } else if (s + 1 < S) {
            asm volatile("cp.async.wait_group 1;");
        } else {
            asm volatile("cp.async.wait_group 0;");
        }
        __syncthreads();
        const int st = s % 3;
        const unsigned* Ad = Asm + st * A_ST;
        const unsigned* Bs = Bsm + st * B_ST;
        #pragma unroll
        for (int ka = 0; ka < 4; ka++) {
            const int kb = ka * 8;
            unsigned af[4][4], bf[8][2];
            #pragma unroll
            for (int mi = 0; mi < 4; mi++) {
                int m0 = warp_m + mi * 16 + r;
                af[mi][0] = Ad[m0 * ASTR + kb + cq];
                af[mi][1] = Ad[(m0 + 8) * ASTR + kb + cq];
                af[mi][2] = Ad[m0 * ASTR + kb + cq + 4];
                af[mi][3] = Ad[(m0 + 8) * ASTR + kb + cq + 4];
            }
            #pragma unroll
            for (int ni = 0; ni < 8; ni++) {
                int n0 = warp_n + ni * 8 + r;
                bf[ni][0] = Bs[(kb + cq) * BSTR + n0];
                bf[ni][1] = Bs[(kb + cq + 4) * BSTR + n0];
            }
            #pragma unroll
            for (int mi = 0; mi < 4; mi++)
                #pragma unroll
                for (int ni = 0; ni < 8; ni++)
                    mma_tf32(acc[mi][ni], af[mi][0], af[mi][1], af[mi][2],
                             af[mi][3], bf[ni][0], bf[ni][1]);
        }
        __syncthreads();
    }

    // ---- epilogue ----
    const int t_z  = dir ? aux.t1 : aux.t0;
    const int tp_z = dir ? aux.tp1 : aux.tp0;
    #pragma unroll
    for (int mi = 0; mi < 4; mi++) {
        #pragma unroll
        for (int ni = 0; ni < 8; ni++) {
            int col = bx * 128 + warp_n + ni * 8 + 2 * cq;
            float bs0 = biasd[col], bs1 = biasd[col + 1];
            #pragma unroll
            for (int half = 0; half < 2; half++) {
                int row = row0 + warp_m + mi * 16 + r + half * 8;
                float v0 = acc[mi][ni][half * 2 + 0] + bs0;
                float v1 = acc[mi][ni][half * 2 + 1] + bs1;
                if (EPI == 0) {
                    float* cp = C + (long)row * N + col;
                    cp[0] = v0; cp[1] = v1;
                } else if (EPI == 1) {
                    unsigned* tp = aux.t1o + (long)row * N + col;
                    tp[0] = f2tf32(gelu_f(v0));
                    tp[1] = f2tf32(gelu_f(v1));
                } else if (EPI == 2) {
                    int lrow = row - dir * 2048;
                    const float* pp = aux.pre
                        + ((long)dir * Lc + t_z) * BNc * D3c
                        + (long)lrow * D3c + col;
                    v0 += pp[0]; v1 += pp[1];
                    if (col < 1536)     v0 = (v0 > 0.f) ? v0 + 1.f : expf(v0);
                    if (col + 1 < 1536) v1 = (v1 > 0.f) ? v1 + 1.f : expf(v1);
                    float* cp = C + (long)row * N + col;
                    cp[0] = v0; cp[1] = v1;
                } else if (EPI == 3) {
                    int lrow = row & 2047;
                    int b = lrow >> 10, rr = lrow & 1023;
                    long xb = (long)b * LNDc + (long)t_z * NDc + (long)rr * Dc + col;
                    long pb = (long)b * LNDc + (long)tp_z * NDc + (long)rr * Dc + col;
                    long idx = (long)row * Dc + col;
                    aux.x2w[idx]     = v0 + aux.X[xb];
                    aux.x2w[idx + 1] = v1 + aux.X[xb + 1];
                    aux.h[idx]     = v0 + aux.h[idx]     + aux.pos[pb];
                    aux.h[idx + 1] = v1 + aux.h[idx + 1] + aux.pos[pb + 1];
                } else if (EPI == 4) {
                    int lrow = row & 2047;
                    int b = lrow >> 10, rr = lrow & 1023;
                    long idx = (long)row * Dc + col;
                    float w0 = v0 + aux.x2r[idx];
                    float w1 = v1 + aux.x2r[idx + 1];
                    long yo = (long)dir * TOTc + (long)b * LNDc
                            + (long)t_z * NDc + (long)rr * Dc + col;
                    aux.y[yo] = w0; aux.y[yo + 1] = w1;
                }
            }
        }
    }
}

// ----------------------- linear-attention small GEMMs ----------------------
__global__ void kv_partial_m(const float* __restrict__ qkvg,
                             float* __restrict__ kvpg) {
    int z = blockIdx.y;
    const float* qkv = qkvg + (long)z * BNc * D3c;
    float* kvp = kvpg + (long)z * Bc * Hc * 8 * 4096;
    int chunk = blockIdx.x & 7;
    int bh = blockIdx.x >> 3;
    int h = bh % Hc, b = bh / Hc;
    int t = threadIdx.x;
    __shared__ float ks[8][64], vs[8][64];
    int d0 = (t & 15) * 4, e0 = (t >> 4) * 4;
    float acc[4][4];
    #pragma unroll
    for (int i = 0; i < 4; i++)
        #pragma unroll
        for (int j = 0; j < 4; j++) acc[i][j] = 0.0f;
    int j0 = chunk * 128;
    const float* kbase = qkv + (long)(b * Nc) * D3c + Dc + h * 64;
    const float* vbase = kbase + Dc;
    for (int js = 0; js < 128; js += 8) {
        #pragma unroll
        for (int rr = 0; rr < 2; rr++) {
            int id = t + rr * 256;
            int jj = id >> 6, dd = id & 63;
            long roff = (long)(j0 + js + jj) * D3c + dd;
            ks[jj][dd] = kbase[roff];
            vs[jj][dd] = vbase[roff];
        }
        __syncthreads();
        #pragma unroll
        for (int jj = 0; jj < 8; jj++) {
            float kd[4], ve[4];
            *(float4*)kd = *(const float4*)&ks[jj][d0];
            *(float4*)ve = *(const float4*)&vs[jj][e0];
            #pragma unroll
            for (int i = 0; i < 4; i++)
                #pragma unroll
                for (int j = 0; j < 4; j++)
                    acc[i][j] = fmaf(kd[i], ve[j], acc[i][j]);
        }
        __syncthreads();
    }
    float* dst = kvp + ((long)bh * 8 + chunk) * 4096;
    #pragma unroll
    for (int i = 0; i < 4; i++)
        #pragma unroll
        for (int j = 0; j < 4; j++)
            dst[(d0 + i) * 64 + e0 + j] = acc[i][j];
}

__global__ void o_kernel_m(const float* __restrict__ qkvg,
                           const float* __restrict__ kvpg,
                           unsigned* __restrict__ og) {
    int z = blockIdx.y;
    const float* qkv = qkvg + (long)z * BNc * D3c;
    const float* kvp = kvpg + (long)z * Bc * Hc * 8 * 4096;
    unsigned* o = og + (long)z * BNDc;
    int ic = blockIdx.x & 7;
    int bh = blockIdx.x >> 3;
    int h = bh % Hc, b = bh / Hc;
    int t = threadIdx.x;
    __shared__ float kvs[4096];
    const float* src = kvp + (long)bh * 8 * 4096;
    for (int x = t; x < 4096; x += 256) {
        float s = 0.0f;
        #pragma unroll
        for (int c = 0; c < 8; c++) s += src[c * 4096 + x];
        kvs[x] = s;
    }
    __syncthreads();
    int i = ic * 128 + (t >> 1);
    int e0 = (t & 1) * 32;
    const float* qrow = qkv + (long)(b * Nc + i) * D3c + h * 64;
    float acc[32];
    #pragma unroll
    for (int g = 0; g < 32; g++) acc[g] = 0.0f;
    #pragma unroll 4
    for (int d = 0; d < 64; d++) {
        float qv = qrow[d];
        #pragma unroll
        for (int g = 0; g < 8; g++) {
            float4 kvv = *(const float4*)&kvs[d * 64 + e0 + g * 4];
            acc[g * 4 + 0] = fmaf(qv, kvv.x, acc[g * 4 + 0]);
            acc[g * 4 + 1] = fmaf(qv, kvv.y, acc[g * 4 + 1]);
            acc[g * 4 + 2] = fmaf(qv, kvv.z, acc[g * 4 + 2]);
            acc[g * 4 + 3] = fmaf(qv, kvv.w, acc[g * 4 + 3]);
        }
    }
    long ob = (long)(b * Nc + i) * Dc + h * 64 + e0;
    #pragma unroll
    for (int g = 0; g < 32; g++) o[ob + g] = f2tf32(acc[g]);
}

// --------------------------------- host ------------------------------------
static inline int cdiv(int a, int b) { return (a + b - 1) / b; }

extern "C" void kernel_launch(void* const* d_in, const int* in_sizes, int n_in,
                              void* d_out, int out_size) {
    (void)in_sizes; (void)n_in; (void)out_size;
    const float* in_x  = (const float*)d_in[0];
    const float* in_h  = (const float*)d_in[1];
    const float* in_sp = (const float*)d_in[2];
    const float* in_tp = (const float*)d_in[3];

    cudaFuncSetAttribute(tgemm<0>, cudaFuncAttributeMaxDynamicSharedMemorySize, TG_SMEM);
    cudaFuncSetAttribute(tgemm<1>, cudaFuncAttributeMaxDynamicSharedMemorySize, TG_SMEM);
    cudaFuncSetAttribute(tgemm<2>, cudaFuncAttributeMaxDynamicSharedMemorySize, TG_SMEM);
    cudaFuncSetAttribute(tgemm<3>, cudaFuncAttributeMaxDynamicSharedMemorySize, TG_SMEM);
    cudaFuncSetAttribute(tgemm<4>, cudaFuncAttributeMaxDynamicSharedMemorySize, TG_SMEM);

    float *pos, *X, *y2, *h, *qkvpre, *qkv, *kvp, *x2;
    unsigned *xnall, *hn, *ln2, *o, *t1;
    unsigned *wq, *wqh, *wo, *w1, *w2;
    cudaGetSymbolAddress((void**)&pos,    g_pos);
    cudaGetSymbolAddress((void**)&X,      g_x);
    cudaGetSymbolAddress((void**)&y2,     g_y2);
    cudaGetSymbolAddress((void**)&h,      g_h);
    cudaGetSymbolAddress((void**)&qkvpre, g_qkvpre);
    cudaGetSymbolAddress((void**)&qkv,    g_qkv);
    cudaGetSymbolAddress((void**)&kvp,    g_kvp);
    cudaGetSymbolAddress((void**)&x2,     g_x2);
    cudaGetSymbolAddress((void**)&xnall,  g_xnall);
    cudaGetSymbolAddress((void**)&hn,     g_hn);
    cudaGetSymbolAddress((void**)&ln2,    g_ln2);
    cudaGetSymbolAddress((void**)&o,      g_o);
    cudaGetSymbolAddress((void**)&t1,     g_t1);
    cudaGetSymbolAddress((void**)&wq,     g_Wqkv);
    cudaGetSymbolAddress((void**)&wqh,    g_Wqkvh);
    cudaGetSymbolAddress((void**)&wo,     g_Wout);
    cudaGetSymbolAddress((void**)&w1,     g_W1);
    cudaGetSymbolAddress((void**)&w2,     g_W2);
    float* out = (float*)d_out;
    float* yf = y2;
    float* yb = y2 + (long)TOTc;

    // prologue
    pos_kernel<<<cdiv(TOTc, 256), 256>>>(in_tp, in_sp, pos);
    vadd_kernel<<<cdiv(TOTc, 256), 256>>>(in_x, pos, X, TOTc);
    wconv_kernel<<<cdiv(4 * Dc * D3c, 256), 256>>>((const float*)d_in[10], wq,  4l * Dc * D3c);
    wconv_kernel<<<cdiv(4 * Dc * D3c, 256), 256>>>((const float*)d_in[12], wqh, 4l * Dc * D3c);
    wconv_kernel<<<cdiv(4 * Dc * Dc,  256), 256>>>((const float*)d_in[14], wo,  4l * Dc * Dc);
    wconv_kernel<<<cdiv(4 * Dc * Mc,  256), 256>>>((const float*)d_in[16], w1,  4l * Dc * Mc);
    wconv_kernel<<<cdiv(4 * Mc * Dc,  256), 256>>>((const float*)d_in[18], w2,  4l * Mc * Dc);

    const long WQZ = 2l * Dc * D3c;   // dir stride in s4 units (s4 = dir*2+layer)
    const long WOZ = 2l * Dc * Dc;
    const long W1Z = 2l * Dc * Mc;
    const long W2Z = 2l * Mc * Dc;

    for (int layer = 0; layer < 2; layer++) {
        const float* lnig = (const float*)d_in[4] + (long)layer * Dc;
        const float* lnib = (const float*)d_in[5] + (long)layer * Dc;
        const float* lnhg = (const float*)d_in[6] + (long)layer * Dc;
        const float* lnhb = (const float*)d_in[7] + (long)layer * Dc;
        const float* lnog = (const float*)d_in[8] + (long)layer * Dc;
        const float* lnob = (const float*)d_in[9] + (long)layer * Dc;
        const float* bqkv  = (const float*)d_in[11] + (long)layer * D3c;
        const float* bqkvh = (const float*)d_in[13] + (long)layer * D3c;
        const float* bout  = (const float*)d_in[15] + (long)layer * Dc;
        const float* b1    = (const float*)d_in[17] + (long)layer * Mc;
        const float* b2    = (const float*)d_in[19] + (long)layer * Dc;
        const unsigned* Wq  = wq  + (long)layer * Dc * D3c;
        const unsigned* Wqh = wqh + (long)layer * Dc * D3c;
        const unsigned* Wo  = wo  + (long)layer * Dc * Dc;
        const unsigned* W1p = w1  + (long)layer * Dc * Mc;
        const unsigned* W2p = w2  + (long)layer * Mc * Dc;

        // batched loop-invariant half, both dirs: pre = LN(x_t)@Wqkv + bqkv
        ln_xall_m<<<2 * BLNc, 256>>>(X, lnig, lnib, xnall);
        {
            EpiAux a = {};
            tgemm<0><<<dim3(D3c / 128, 2 * BLNc / 128), 128, TG_SMEM>>>(
                xnall, Dc, Wq, WQZ, D3c, bqkv, 2 * D3c,
                qkvpre, D3c, Dc, BLNc, a);
        }
        hinit_kernel<<<cdiv(BNDc, 256), 256>>>(in_h, h);

        for (int ss = 0; ss < Lc; ss++) {
            int t0 = ss, t1s = Lc - 1 - ss;
            int tp0 = layer, tp1 = t1s;   // ref quirk: fwd uses pos[:, layer]

            ln_h_m<<<2 * BNc, 256>>>(h, pos, tp0, tp1, lnhg, lnhb, hn);

            EpiAux a2 = {};
            a2.pre = qkvpre; a2.t0 = t0; a2.t1 = t1s;
            tgemm<2><<<dim3(D3c / 128, 2 * BNc / 128), 128, TG_SMEM>>>(
                hn, Dc, Wqh, WQZ, D3c, bqkvh, 2 * D3c,
                qkv, D3c, Dc, BNc, a2);

            kv_partial_m<<<dim3(Bc * Hc * 8, 2), 256>>>(qkv, kvp);
            o_kernel_m<<<dim3(Bc * Hc * 8, 2), 256>>>(qkv, kvp, o);

            EpiAux a3 = {};
            a3.t0 = t0; a3.t1 = t1s; a3.X = X; a3.h = h;
            a3.pos = pos; a3.tp0 = tp0; a3.tp1 = tp1; a3.x2w = x2;
            tgemm<3><<<dim3(Dc / 128, 2 * BNc / 128), 128, TG_SMEM>>>(
                o, Dc, Wo, WOZ, Dc, bout, 2 * Dc,
                x2, Dc, Dc, BNc, a3);

            ln2_m<<<2 * BNc, 256>>>(x2, lnog, lnob, ln2);

            EpiAux a1 = {};
            a1.t1o = t1;
            tgemm<1><<<dim3(Mc / 128, 2 * BNc / 128), 128, TG_SMEM>>>(
                ln2, Dc, W1p, W1Z, Mc, b1, 2 * Mc,
                nullptr, Mc, Dc, BNc, a1);

            EpiAux a4 = {};
            a4.t0 = t0; a4.t1 = t1s; a4.x2r = x2; a4.y = y2;
            tgemm<4><<<dim3(Dc / 128, 2 * BNc / 128), 128, TG_SMEM>>>(
                t1, Mc, W2p, W2Z, Dc, b2, 2 * Dc,
                nullptr, Dc, Mc, BNc, a4);
        }

        if (layer == 0)
            combine_kernel<<<cdiv(TOTc, 256), 256>>>(yf, yb, pos, X, TOTc);
        else
            combine_kernel<<<cdiv(TOTc, 256), 256>>>(yf, yb, nullptr, out, TOTc);
    }
}